// round 2
// baseline (speedup 1.0000x reference)
#include <cuda_runtime.h>
#include <cstdint>

#define NN 100000
#define NE 1600000

// ---------------- scratch (device globals; no allocations allowed) ----------
__device__ __align__(16) float g_deg [NN];
__device__ __align__(16) float g_acc0[NN * 48];
__device__ __align__(16) float g_hin [NN * 192];  // [h(96) | mean_neigh_h(96)]
__device__ __align__(16) float g_acc1[NN * 96];
__device__ __align__(16) float g_h1  [NN * 128];
__device__ __align__(16) float g_q   [NN * 64];   // h1 @ W2s
__device__ __align__(16) float g_p2  [NN * 64];   // h1 @ W2n (pushed before aggregation)
__device__ __align__(16) float g_acc2[NN * 64];

// 16B vector reduction to global (sm_90+)
__device__ __forceinline__ void red_add_v4(float* p, float4 v) {
    asm volatile("red.global.add.v4.f32 [%0], {%1, %2, %3, %4};"
                 :: "l"(p), "f"(v.x), "f"(v.y), "f"(v.z), "f"(v.w) : "memory");
}

// ---------------- K0: zero accumulators -------------------------------------
__global__ void k_zero() {
    int idx = blockIdx.x * blockDim.x + threadIdx.x;
    int stride = gridDim.x * blockDim.x;
    float4 z = make_float4(0.f, 0.f, 0.f, 0.f);
    for (int i = idx; i < NN * 48 / 4; i += stride) ((float4*)g_acc0)[i] = z;
    for (int i = idx; i < NN * 96 / 4; i += stride) ((float4*)g_acc1)[i] = z;
    for (int i = idx; i < NN * 64 / 4; i += stride) ((float4*)g_acc2)[i] = z;
    for (int i = idx; i < NN / 4;      i += stride) ((float4*)g_deg)[i]  = z;
}

// ---------------- K1: edge encoder + u_mul_e message + scatter ---------------
// One thread per edge. e = relu(efeat @ We + be); m = nfeat[src] * e; acc0[dst] += m.
__global__ void __launch_bounds__(128) k_edge0(
    const float* __restrict__ efeat, const float* __restrict__ nfeat,
    const int* __restrict__ src, const int* __restrict__ dst,
    const float* __restrict__ We, const float* __restrict__ be)
{
    __shared__ float sW[32 * 48];
    __shared__ float sB[48];
    for (int i = threadIdx.x; i < 32 * 48; i += 128) sW[i] = We[i];
    if (threadIdx.x < 48) sB[threadIdx.x] = be[threadIdx.x];
    __syncthreads();

    int e = blockIdx.x * 128 + threadIdx.x;
    if (e >= NE) return;

    int s = src[e], d = dst[e];
    float ef[32];
    const float4* efp = (const float4*)(efeat + (size_t)e * 32);
#pragma unroll
    for (int k = 0; k < 8; k++) {
        float4 t = efp[k];
        ef[4*k] = t.x; ef[4*k+1] = t.y; ef[4*k+2] = t.z; ef[4*k+3] = t.w;
    }
    atomicAdd(&g_deg[d], 1.0f);

    const float4* nf = (const float4*)(nfeat + (size_t)s * 48);
    float* outp = g_acc0 + (size_t)d * 48;

#pragma unroll
    for (int jb = 0; jb < 12; jb++) {
        float4 a = ((const float4*)sB)[jb];
#pragma unroll
        for (int k = 0; k < 32; k++) {
            float4 w = *(const float4*)(sW + k * 48 + jb * 4);
            a.x = fmaf(ef[k], w.x, a.x);
            a.y = fmaf(ef[k], w.y, a.y);
            a.z = fmaf(ef[k], w.z, a.z);
            a.w = fmaf(ef[k], w.w, a.w);
        }
        float4 nv = nf[jb];
        a.x = fmaxf(a.x, 0.f) * nv.x;
        a.y = fmaxf(a.y, 0.f) * nv.y;
        a.z = fmaxf(a.z, 0.f) * nv.z;
        a.w = fmaxf(a.w, 0.f) * nv.w;
        red_add_v4(outp + jb * 4, a);
    }
}

// ---------------- K2: g_hin[:, 0:96] = [nfeat | acc0/deg] --------------------
__global__ void k_build_h(const float* __restrict__ nfeat) {
    int idx = blockIdx.x * blockDim.x + threadIdx.x;
    if (idx >= NN * 24) return;
    int n = idx / 24, c = idx - n * 24;
    float4 v;
    if (c < 12) {
        v = ((const float4*)nfeat)[(size_t)n * 12 + c];
    } else {
        float inv = 1.0f / fmaxf(g_deg[n], 1.0f);
        float4 t = ((const float4*)g_acc0)[(size_t)n * 12 + (c - 12)];
        v.x = t.x * inv; v.y = t.y * inv; v.z = t.z * inv; v.w = t.w * inv;
    }
    ((float4*)(g_hin + (size_t)n * 192))[c] = v;
}

// ---------------- K3: gather h[src] -> acc1[dst]  (96 floats = 24 chunks) ----
__global__ void k_edge1(const int* __restrict__ src, const int* __restrict__ dst) {
    int idx = blockIdx.x * blockDim.x + threadIdx.x;
    if (idx >= NE * 24) return;
    int e = idx / 24, c = idx - e * 24;
    int s = src[e], d = dst[e];
    float4 v = ((const float4*)(g_hin + (size_t)s * 192))[c];
    red_add_v4(g_acc1 + (size_t)d * 96 + c * 4, v);
}

// ---------------- K4: g_hin[:, 96:192] = acc1/deg ----------------------------
__global__ void k_norm1() {
    int idx = blockIdx.x * blockDim.x + threadIdx.x;
    if (idx >= NN * 24) return;
    int n = idx / 24, c = idx - n * 24;
    float inv = 1.0f / fmaxf(g_deg[n], 1.0f);
    float4 t = ((const float4*)g_acc1)[(size_t)n * 24 + c];
    float4 v;
    v.x = t.x * inv; v.y = t.y * inv; v.z = t.z * inv; v.w = t.w * inv;
    ((float4*)(g_hin + (size_t)n * 192 + 96))[c] = v;
}

// ---------------- K5: h1 = relu(g_hin @ [W1s;W1n] + b1) ----------------------
// 256 threads; K tiled in 3 chunks of 64 (weights tile 32KB static smem).
// Each thread: 1 output column x 16 nodes, register accumulators across tiles.
__global__ void __launch_bounds__(256) k_gemm1(
    const float* __restrict__ W1s, const float* __restrict__ W1n,
    const float* __restrict__ b1)
{
    __shared__ float sW[64 * 128];   // 32 KB
    __shared__ float sIn[32 * 64];   // 8 KB
    __shared__ float sB[128];
    if (threadIdx.x < 128) sB[threadIdx.x] = b1[threadIdx.x];

    int out = threadIdx.x & 127;
    int sub = threadIdx.x >> 7;      // node subset: 0 -> nodes 0..15, 1 -> 16..31

    for (int g = blockIdx.x; g < NN / 32; g += gridDim.x) {
        int nb = g * 32;
        float acc[16];
#pragma unroll
        for (int n = 0; n < 16; n++) acc[n] = 0.f;

        for (int kt = 0; kt < 3; kt++) {
            __syncthreads();
            for (int i = threadIdx.x; i < 64 * 128; i += 256) {
                int r = i >> 7, c = i & 127;
                int gk = kt * 64 + r;
                sW[i] = (gk < 96) ? W1s[gk * 128 + c] : W1n[(gk - 96) * 128 + c];
            }
            for (int i = threadIdx.x; i < 512; i += 256) {
                int m = i >> 4, c4 = i & 15;
                ((float4*)sIn)[i] =
                    *(const float4*)(g_hin + (size_t)(nb + m) * 192 + kt * 64 + c4 * 4);
            }
            __syncthreads();

            const float* xb0 = sIn + sub * 16 * 64;
#pragma unroll
            for (int k = 0; k < 64; k += 4) {
                float w0 = sW[(k + 0) * 128 + out];
                float w1 = sW[(k + 1) * 128 + out];
                float w2 = sW[(k + 2) * 128 + out];
                float w3 = sW[(k + 3) * 128 + out];
#pragma unroll
                for (int n = 0; n < 16; n++) {
                    float4 x = *(const float4*)(xb0 + n * 64 + k);
                    acc[n] = fmaf(x.x, w0, acc[n]);
                    acc[n] = fmaf(x.y, w1, acc[n]);
                    acc[n] = fmaf(x.z, w2, acc[n]);
                    acc[n] = fmaf(x.w, w3, acc[n]);
                }
            }
        }
        float b = sB[out];
#pragma unroll
        for (int n = 0; n < 16; n++)
            g_h1[(size_t)(nb + sub * 16 + n) * 128 + out] = fmaxf(acc[n] + b, 0.f);
    }
}

// ---------------- K6: q = h1@W2s (cols 0..63), p2 = h1@W2n (cols 64..127) ----
__global__ void __launch_bounds__(256) k_gemm2(
    const float* __restrict__ W2s, const float* __restrict__ W2n)
{
    __shared__ float sW[64 * 128];   // 32 KB
    __shared__ float sIn[32 * 64];   // 8 KB

    int out = threadIdx.x & 127;
    int sub = threadIdx.x >> 7;

    for (int g = blockIdx.x; g < NN / 32; g += gridDim.x) {
        int nb = g * 32;
        float acc[16];
#pragma unroll
        for (int n = 0; n < 16; n++) acc[n] = 0.f;

        for (int kt = 0; kt < 2; kt++) {
            __syncthreads();
            for (int i = threadIdx.x; i < 64 * 128; i += 256) {
                int r = i >> 7, c = i & 127;
                int gk = kt * 64 + r;
                sW[i] = (c < 64) ? W2s[gk * 64 + c] : W2n[gk * 64 + (c - 64)];
            }
            for (int i = threadIdx.x; i < 512; i += 256) {
                int m = i >> 4, c4 = i & 15;
                ((float4*)sIn)[i] =
                    *(const float4*)(g_h1 + (size_t)(nb + m) * 128 + kt * 64 + c4 * 4);
            }
            __syncthreads();

            const float* xb0 = sIn + sub * 16 * 64;
#pragma unroll
            for (int k = 0; k < 64; k += 4) {
                float w0 = sW[(k + 0) * 128 + out];
                float w1 = sW[(k + 1) * 128 + out];
                float w2 = sW[(k + 2) * 128 + out];
                float w3 = sW[(k + 3) * 128 + out];
#pragma unroll
                for (int n = 0; n < 16; n++) {
                    float4 x = *(const float4*)(xb0 + n * 64 + k);
                    acc[n] = fmaf(x.x, w0, acc[n]);
                    acc[n] = fmaf(x.y, w1, acc[n]);
                    acc[n] = fmaf(x.z, w2, acc[n]);
                    acc[n] = fmaf(x.w, w3, acc[n]);
                }
            }
        }
        float* dstA = (out < 64) ? g_q : g_p2;
        int col = out & 63;
#pragma unroll
        for (int n = 0; n < 16; n++)
            dstA[(size_t)(nb + sub * 16 + n) * 64 + col] = acc[n];
    }
}

// ---------------- K7: gather p2[src] -> acc2[dst]  (64 floats = 16 chunks) ---
__global__ void k_edge2(const int* __restrict__ src, const int* __restrict__ dst) {
    int idx = blockIdx.x * blockDim.x + threadIdx.x;
    if (idx >= NE * 16) return;
    int e = idx >> 4, c = idx & 15;
    int s = src[e], d = dst[e];
    float4 v = ((const float4*)g_p2)[(size_t)s * 16 + c];
    red_add_v4(g_acc2 + (size_t)d * 64 + c * 4, v);
}

// ---------------- K8: out = q + acc2/deg + b2 --------------------------------
__global__ void k_final(const float* __restrict__ b2, float* __restrict__ outp) {
    int idx = blockIdx.x * blockDim.x + threadIdx.x;
    if (idx >= NN * 16) return;
    int n = idx >> 4, c = idx & 15;
    float inv = 1.0f / fmaxf(g_deg[n], 1.0f);
    float4 q  = ((const float4*)g_q)[idx];
    float4 a  = ((const float4*)g_acc2)[idx];
    float4 bb = ((const float4*)b2)[c];
    float4 r;
    r.x = q.x + a.x * inv + bb.x;
    r.y = q.y + a.y * inv + bb.y;
    r.z = q.z + a.z * inv + bb.z;
    r.w = q.w + a.w * inv + bb.w;
    ((float4*)outp)[idx] = r;
}

// ---------------- launch -----------------------------------------------------
extern "C" void kernel_launch(void* const* d_in, const int* in_sizes, int n_in,
                              void* d_out, int out_size)
{
    const float* nfeat = (const float*)d_in[0];
    const float* efeat = (const float*)d_in[1];
    const int*   src   = (const int*)  d_in[2];
    const int*   dst   = (const int*)  d_in[3];
    const float* We    = (const float*)d_in[4];
    const float* be    = (const float*)d_in[5];
    const float* W1s   = (const float*)d_in[6];
    const float* W1n   = (const float*)d_in[7];
    const float* b1    = (const float*)d_in[8];
    const float* W2s   = (const float*)d_in[9];
    const float* W2n   = (const float*)d_in[10];
    const float* b2    = (const float*)d_in[11];
    float* out = (float*)d_out;

    k_zero<<<2048, 256>>>();
    k_edge0<<<NE / 128, 128>>>(efeat, nfeat, src, dst, We, be);
    k_build_h<<<(NN * 24 + 255) / 256, 256>>>(nfeat);
    k_edge1<<<(NE * 24 + 255) / 256, 256>>>(src, dst);
    k_norm1<<<(NN * 24 + 255) / 256, 256>>>();
    k_gemm1<<<592, 256>>>(W1s, W1n, b1);
    k_gemm2<<<592, 256>>>(W2s, W2n);
    k_edge2<<<(NE * 16 + 255) / 256, 256>>>(src, dst);
    k_final<<<(NN * 16 + 255) / 256, 256>>>(b2, out);
}

// round 3
// speedup vs baseline: 1.2137x; 1.2137x over previous
#include <cuda_runtime.h>
#include <cstdint>

#define NN 100000
#define NP 100032          // padded to multiple of 64 for GEMM tiles
#define NE 1600000

// ---------------- scratch (device globals; no allocations allowed) ----------
__device__ __align__(16) float g_deg [NN];
__device__ __align__(16) float g_acc0[NN * 48];
__device__ __align__(16) float g_hin [NP * 192];  // [h(96) | mean_neigh_h(96)]
__device__ __align__(16) float g_acc1[NN * 96];
__device__ __align__(16) float g_h1  [NP * 128];
__device__ __align__(16) float g_q   [NP * 64];   // h1 @ W2s
__device__ __align__(16) float g_p2  [NP * 64];   // h1 @ W2n (pushed before aggregation)
__device__ __align__(16) float g_acc2[NN * 64];

// 16B vector reduction to global (sm_90+)
__device__ __forceinline__ void red_add_v4(float* p, float4 v) {
    asm volatile("red.global.add.v4.f32 [%0], {%1, %2, %3, %4};"
                 :: "l"(p), "f"(v.x), "f"(v.y), "f"(v.z), "f"(v.w) : "memory");
}

// ---------------- K0: zero accumulators -------------------------------------
__global__ void k_zero() {
    int idx = blockIdx.x * blockDim.x + threadIdx.x;
    int stride = gridDim.x * blockDim.x;
    float4 z = make_float4(0.f, 0.f, 0.f, 0.f);
    for (int i = idx; i < NN * 48 / 4; i += stride) ((float4*)g_acc0)[i] = z;
    for (int i = idx; i < NN * 96 / 4; i += stride) ((float4*)g_acc1)[i] = z;
    for (int i = idx; i < NN * 64 / 4; i += stride) ((float4*)g_acc2)[i] = z;
    for (int i = idx; i < NN / 4;      i += stride) ((float4*)g_deg)[i]  = z;
}

// ---------------- K1: edge encoder + u_mul_e message + scatter ---------------
// One thread per edge. e = relu(efeat @ We + be); m = nfeat[src] * e;
// acc0[dst] += m;  acc1[dst][0:48] += nfeat[src]  (layer-1 self-half of h[src] sum)
__global__ void __launch_bounds__(128) k_edge0(
    const float* __restrict__ efeat, const float* __restrict__ nfeat,
    const int* __restrict__ src, const int* __restrict__ dst,
    const float* __restrict__ We, const float* __restrict__ be)
{
    __shared__ float sW[32 * 48];
    __shared__ float sB[48];
    for (int i = threadIdx.x; i < 32 * 48; i += 128) sW[i] = We[i];
    if (threadIdx.x < 48) sB[threadIdx.x] = be[threadIdx.x];
    __syncthreads();

    int e = blockIdx.x * 128 + threadIdx.x;
    if (e >= NE) return;

    int s = src[e], d = dst[e];
    float ef[32];
    const float4* efp = (const float4*)(efeat + (size_t)e * 32);
#pragma unroll
    for (int k = 0; k < 8; k++) {
        float4 t = efp[k];
        ef[4*k] = t.x; ef[4*k+1] = t.y; ef[4*k+2] = t.z; ef[4*k+3] = t.w;
    }
    atomicAdd(&g_deg[d], 1.0f);

    const float4* nf = (const float4*)(nfeat + (size_t)s * 48);
    float* out0 = g_acc0 + (size_t)d * 48;
    float* out1 = g_acc1 + (size_t)d * 96;

#pragma unroll
    for (int jb = 0; jb < 12; jb++) {
        float4 a = ((const float4*)sB)[jb];
#pragma unroll
        for (int k = 0; k < 32; k++) {
            float4 w = *(const float4*)(sW + k * 48 + jb * 4);
            a.x = fmaf(ef[k], w.x, a.x);
            a.y = fmaf(ef[k], w.y, a.y);
            a.z = fmaf(ef[k], w.z, a.z);
            a.w = fmaf(ef[k], w.w, a.w);
        }
        float4 nv = nf[jb];
        a.x = fmaxf(a.x, 0.f) * nv.x;
        a.y = fmaxf(a.y, 0.f) * nv.y;
        a.z = fmaxf(a.z, 0.f) * nv.z;
        a.w = fmaxf(a.w, 0.f) * nv.w;
        red_add_v4(out0 + jb * 4, a);
        red_add_v4(out1 + jb * 4, nv);
    }
}

// ---------------- K2: g_hin[:, 0:96] = [nfeat | acc0/deg] --------------------
__global__ void k_build_h(const float* __restrict__ nfeat) {
    int idx = blockIdx.x * blockDim.x + threadIdx.x;
    if (idx >= NN * 24) return;
    int n = idx / 24, c = idx - n * 24;
    float4 v;
    if (c < 12) {
        v = ((const float4*)nfeat)[(size_t)n * 12 + c];
    } else {
        float inv = 1.0f / fmaxf(g_deg[n], 1.0f);
        float4 t = ((const float4*)g_acc0)[(size_t)n * 12 + (c - 12)];
        v.x = t.x * inv; v.y = t.y * inv; v.z = t.z * inv; v.w = t.w * inv;
    }
    ((float4*)(g_hin + (size_t)n * 192))[c] = v;
}

// ---------------- K3: gather h_neigh0[src] -> acc1[dst][48:96] ---------------
__global__ void k_edge1(const int* __restrict__ src, const int* __restrict__ dst) {
    int idx = blockIdx.x * blockDim.x + threadIdx.x;
    if (idx >= NE * 12) return;
    int e = idx / 12, c = idx - e * 12;
    int s = src[e], d = dst[e];
    float4 v = ((const float4*)(g_hin + (size_t)s * 192 + 48))[c];
    red_add_v4(g_acc1 + (size_t)d * 96 + 48 + c * 4, v);
}

// ---------------- K4: g_hin[:, 96:192] = acc1/deg ----------------------------
__global__ void k_norm1() {
    int idx = blockIdx.x * blockDim.x + threadIdx.x;
    if (idx >= NN * 24) return;
    int n = idx / 24, c = idx - n * 24;
    float inv = 1.0f / fmaxf(g_deg[n], 1.0f);
    float4 t = ((const float4*)g_acc1)[(size_t)n * 24 + c];
    float4 v;
    v.x = t.x * inv; v.y = t.y * inv; v.z = t.z * inv; v.w = t.w * inv;
    ((float4*)(g_hin + (size_t)n * 192 + 96))[c] = v;
}

// ---------------- K5: h1 = relu(g_hin @ [W1s;W1n] + b1) ----------------------
// 64-node x 128-col tile, 256 threads, 8n x 4c register blocking (32 acc).
// x tile stored k-major in smem -> broadcast LDS.128 in compute.
__global__ void __launch_bounds__(256) k_gemm1(
    const float* __restrict__ W1s, const float* __restrict__ W1n,
    const float* __restrict__ b1)
{
    __shared__ float sW [64 * 128];   // 32 KB  [k][c]
    __shared__ float sXT[64 * 64];    // 16 KB  [k][n]
    int t = threadIdx.x;
    int cgrp = t & 31;                // cols cgrp*4 .. +3
    int ngrp = t >> 5;                // nodes ngrp*8 .. +7 (uniform per warp)
    float4 bias = *(const float4*)(b1 + cgrp * 4);

    int nb = blockIdx.x * 64;
    float acc[8][4];
#pragma unroll
    for (int n = 0; n < 8; n++)
#pragma unroll
        for (int c = 0; c < 4; c++) acc[n][c] = 0.f;

    for (int kt = 0; kt < 3; kt++) {
        __syncthreads();
        for (int i = t; i < 64 * 32; i += 256) {           // weights: f4 granularity
            int r = i >> 5, c4 = i & 31;
            int gk = kt * 64 + r;
            float4 w = (gk < 96) ? *(const float4*)(W1s + gk * 128 + c4 * 4)
                                 : *(const float4*)(W1n + (gk - 96) * 128 + c4 * 4);
            ((float4*)sW)[i] = w;
        }
        for (int i = t; i < 64 * 16; i += 256) {           // x transpose load
            int n = i & 63, kq = i >> 6;
            float4 x = *(const float4*)(g_hin + (size_t)(nb + n) * 192 + kt * 64 + kq * 4);
            sXT[(kq * 4 + 0) * 64 + n] = x.x;
            sXT[(kq * 4 + 1) * 64 + n] = x.y;
            sXT[(kq * 4 + 2) * 64 + n] = x.z;
            sXT[(kq * 4 + 3) * 64 + n] = x.w;
        }
        __syncthreads();

#pragma unroll 8
        for (int k = 0; k < 64; k++) {
            float4 w  = *(const float4*)(sW  + k * 128 + cgrp * 4);
            float4 x0 = *(const float4*)(sXT + k * 64 + ngrp * 8);
            float4 x1 = *(const float4*)(sXT + k * 64 + ngrp * 8 + 4);
            float xs[8] = {x0.x, x0.y, x0.z, x0.w, x1.x, x1.y, x1.z, x1.w};
#pragma unroll
            for (int n = 0; n < 8; n++) {
                acc[n][0] = fmaf(xs[n], w.x, acc[n][0]);
                acc[n][1] = fmaf(xs[n], w.y, acc[n][1]);
                acc[n][2] = fmaf(xs[n], w.z, acc[n][2]);
                acc[n][3] = fmaf(xs[n], w.w, acc[n][3]);
            }
        }
    }
#pragma unroll
    for (int n = 0; n < 8; n++) {
        float4 r;
        r.x = fmaxf(acc[n][0] + bias.x, 0.f);
        r.y = fmaxf(acc[n][1] + bias.y, 0.f);
        r.z = fmaxf(acc[n][2] + bias.z, 0.f);
        r.w = fmaxf(acc[n][3] + bias.w, 0.f);
        *(float4*)(g_h1 + (size_t)(nb + ngrp * 8 + n) * 128 + cgrp * 4) = r;
    }
}

// ---------------- K6: q = h1@W2s (cols 0..63), p2 = h1@W2n (cols 64..127) ----
__global__ void __launch_bounds__(256) k_gemm2(
    const float* __restrict__ W2s, const float* __restrict__ W2n)
{
    __shared__ float sW [64 * 128];   // 32 KB [k][c]  (c<64: W2s, c>=64: W2n)
    __shared__ float sXT[64 * 64];    // 16 KB [k][n]
    int t = threadIdx.x;
    int cgrp = t & 31;
    int ngrp = t >> 5;

    int nb = blockIdx.x * 64;
    float acc[8][4];
#pragma unroll
    for (int n = 0; n < 8; n++)
#pragma unroll
        for (int c = 0; c < 4; c++) acc[n][c] = 0.f;

    for (int kt = 0; kt < 2; kt++) {
        __syncthreads();
        for (int i = t; i < 64 * 32; i += 256) {
            int r = i >> 5, c4 = i & 31;
            int gk = kt * 64 + r;
            float4 w = (c4 < 16) ? *(const float4*)(W2s + gk * 64 + c4 * 4)
                                 : *(const float4*)(W2n + gk * 64 + (c4 - 16) * 4);
            ((float4*)sW)[i] = w;
        }
        for (int i = t; i < 64 * 16; i += 256) {
            int n = i & 63, kq = i >> 6;
            float4 x = *(const float4*)(g_h1 + (size_t)(nb + n) * 128 + kt * 64 + kq * 4);
            sXT[(kq * 4 + 0) * 64 + n] = x.x;
            sXT[(kq * 4 + 1) * 64 + n] = x.y;
            sXT[(kq * 4 + 2) * 64 + n] = x.z;
            sXT[(kq * 4 + 3) * 64 + n] = x.w;
        }
        __syncthreads();

#pragma unroll 8
        for (int k = 0; k < 64; k++) {
            float4 w  = *(const float4*)(sW  + k * 128 + cgrp * 4);
            float4 x0 = *(const float4*)(sXT + k * 64 + ngrp * 8);
            float4 x1 = *(const float4*)(sXT + k * 64 + ngrp * 8 + 4);
            float xs[8] = {x0.x, x0.y, x0.z, x0.w, x1.x, x1.y, x1.z, x1.w};
#pragma unroll
            for (int n = 0; n < 8; n++) {
                acc[n][0] = fmaf(xs[n], w.x, acc[n][0]);
                acc[n][1] = fmaf(xs[n], w.y, acc[n][1]);
                acc[n][2] = fmaf(xs[n], w.z, acc[n][2]);
                acc[n][3] = fmaf(xs[n], w.w, acc[n][3]);
            }
        }
    }
    float* dstA = (cgrp < 16) ? g_q : g_p2;
    int col = (cgrp & 15) * 4;
#pragma unroll
    for (int n = 0; n < 8; n++) {
        float4 r = make_float4(acc[n][0], acc[n][1], acc[n][2], acc[n][3]);
        *(float4*)(dstA + (size_t)(nb + ngrp * 8 + n) * 64 + col) = r;
    }
}

// ---------------- K7: gather p2[src] -> acc2[dst]  (64 floats = 16 chunks) ---
__global__ void k_edge2(const int* __restrict__ src, const int* __restrict__ dst) {
    int idx = blockIdx.x * blockDim.x + threadIdx.x;
    if (idx >= NE * 16) return;
    int e = idx >> 4, c = idx & 15;
    int s = src[e], d = dst[e];
    float4 v = ((const float4*)g_p2)[(size_t)s * 16 + c];
    red_add_v4(g_acc2 + (size_t)d * 64 + c * 4, v);
}

// ---------------- K8: out = q + acc2/deg + b2 --------------------------------
__global__ void k_final(const float* __restrict__ b2, float* __restrict__ outp) {
    int idx = blockIdx.x * blockDim.x + threadIdx.x;
    if (idx >= NN * 16) return;
    int n = idx >> 4, c = idx & 15;
    float inv = 1.0f / fmaxf(g_deg[n], 1.0f);
    float4 q  = ((const float4*)g_q)[(size_t)n * 16 + c];
    float4 a  = ((const float4*)g_acc2)[(size_t)n * 16 + c];
    float4 bb = ((const float4*)b2)[c];
    float4 r;
    r.x = q.x + a.x * inv + bb.x;
    r.y = q.y + a.y * inv + bb.y;
    r.z = q.z + a.z * inv + bb.z;
    r.w = q.w + a.w * inv + bb.w;
    ((float4*)outp)[idx] = r;
}

// ---------------- launch -----------------------------------------------------
extern "C" void kernel_launch(void* const* d_in, const int* in_sizes, int n_in,
                              void* d_out, int out_size)
{
    const float* nfeat = (const float*)d_in[0];
    const float* efeat = (const float*)d_in[1];
    const int*   src   = (const int*)  d_in[2];
    const int*   dst   = (const int*)  d_in[3];
    const float* We    = (const float*)d_in[4];
    const float* be    = (const float*)d_in[5];
    const float* W1s   = (const float*)d_in[6];
    const float* W1n   = (const float*)d_in[7];
    const float* b1    = (const float*)d_in[8];
    const float* W2s   = (const float*)d_in[9];
    const float* W2n   = (const float*)d_in[10];
    const float* b2    = (const float*)d_in[11];
    float* out = (float*)d_out;

    k_zero<<<2048, 256>>>();
    k_edge0<<<NE / 128, 128>>>(efeat, nfeat, src, dst, We, be);
    k_build_h<<<(NN * 24 + 255) / 256, 256>>>(nfeat);
    k_edge1<<<(NE * 12 + 255) / 256, 256>>>(src, dst);
    k_norm1<<<(NN * 24 + 255) / 256, 256>>>();
    k_gemm1<<<NP / 64, 256>>>(W1s, W1n, b1);
    k_gemm2<<<NP / 64, 256>>>(W2s, W2n);
    k_edge2<<<(NE * 16 + 255) / 256, 256>>>(src, dst);
    k_final<<<(NN * 16 + 255) / 256, 256>>>(b2, out);
}